// round 14
// baseline (speedup 1.0000x reference)
#include <cuda_runtime.h>
#include <cuda_fp16.h>
#include <cstdint>
#include <math.h>
#include <mma.h>

using namespace nvcuda;

#define DIM 128

// ---------------- scratch (device globals; no allocation allowed) ----------------
__device__ int    g_deg [600000];
__device__ float  g_norm[600000];
__device__ int    g_base  [300000];   // CSR row starts: [dd | gd | dg | gg] (by dst)
__device__ int    g_cursor[300000];
__device__ int    g_bsum  [512];
__device__ int    g_ebuf  [2400000];  // binned src indices
__device__ __half g_hD[100000ull * 256];  // drug proj: cols 0-127 = dd, 128-255 = dg
__device__ __half g_hG[ 50000ull * 256];  // gene proj: cols 0-127 = gd, 128-255 = gg

// ---------------- zero deg ----------------
__global__ void zero_deg() {
    int i = blockIdx.x * blockDim.x + threadIdx.x;
    if (i < 600000 / 4) ((int4*)g_deg)[i] = make_int4(0, 0, 0, 0);
}

// ---------------- degree counting (all 4 etypes) ----------------
__global__ void deg_all(const int* __restrict__ s0, const int* __restrict__ d0, int o0s, int o0d,
                        const int* __restrict__ s1, const int* __restrict__ d1, int o1s, int o1d,
                        const int* __restrict__ s2, const int* __restrict__ d2, int o2s, int o2d,
                        const int* __restrict__ s3, const int* __restrict__ d3, int o3s, int o3d,
                        int E) {
    int i = blockIdx.x * blockDim.x + threadIdx.x;
    const int *s, *d; int os, od, j;
    if (i < E)          { s = s0; d = d0; os = o0s; od = o0d; j = i; }
    else if (i < 2 * E) { s = s1; d = d1; os = o1s; od = o1d; j = i - E; }
    else if (i < 3 * E) { s = s2; d = d2; os = o2s; od = o2d; j = i - 2 * E; }
    else if (i < 4 * E) { s = s3; d = d3; os = o3s; od = o3d; j = i - 3 * E; }
    else return;
    atomicAdd(&g_deg[os + __ldg(s + j)], 1);
    atomicAdd(&g_deg[od + __ldg(d + j)], 1);
}

__global__ void norm_kernel(int n) {
    int i = blockIdx.x * blockDim.x + threadIdx.x;
    if (i < n) g_norm[i] = rsqrtf(fmaxf((float)g_deg[i], 1.0f));
}

// ---------------- 3-phase exclusive scan over concatenated dst degrees ----------------
#define SCAN_BLK 1024
__global__ void scan1(int total, int nDrug, int nGene,
                      int o_dd_d, int o_gd_d, int o_dg_d, int o_gg_d) {
    __shared__ int sh[256];
    const int tid = threadIdx.x;
    const int base = blockIdx.x * SCAN_BLK + tid * 4;
    const int c1 = nDrug, c2 = 2 * nDrug, c3 = 2 * nDrug + nGene;
    int v[4], ssum = 0;
    #pragma unroll
    for (int q = 0; q < 4; q++) {
        int i = base + q, d = 0;
        if (i < total) {
            int idx;
            if (i < c1)      idx = o_dd_d + i;
            else if (i < c2) idx = o_gd_d + i - c1;
            else if (i < c3) idx = o_dg_d + i - c2;
            else             idx = o_gg_d + i - c3;
            d = g_deg[idx];
        }
        v[q] = d; ssum += d;
    }
    sh[tid] = ssum; __syncthreads();
    for (int off = 1; off < 256; off <<= 1) {
        int t = (tid >= off) ? sh[tid - off] : 0;
        __syncthreads();
        sh[tid] += t;
        __syncthreads();
    }
    int run = sh[tid] - ssum;
    if (tid == 255) g_bsum[blockIdx.x] = sh[255];
    #pragma unroll
    for (int q = 0; q < 4; q++) {
        int i = base + q;
        if (i < total) g_base[i] = run;
        run += v[q];
    }
}

__global__ void scan2(int n) {
    __shared__ int sh[512];
    int tid = threadIdx.x;
    int v = (tid < n) ? g_bsum[tid] : 0;
    sh[tid] = v; __syncthreads();
    for (int off = 1; off < 512; off <<= 1) {
        int t = (tid >= off) ? sh[tid - off] : 0;
        __syncthreads();
        sh[tid] += t;
        __syncthreads();
    }
    if (tid < n) g_bsum[tid] = sh[tid] - v;
}

__global__ void scan3(int total) {
    int i = blockIdx.x * blockDim.x + threadIdx.x;
    if (i < total) {
        int v = g_base[i] + g_bsum[i / SCAN_BLK];
        g_base[i] = v;
        g_cursor[i] = v;
    }
}

// ---------------- binning: ebuf[pos] = src (CSR by dst); segment order dd, gd, dg, gg ----------------
__global__ void bin_all(const int* __restrict__ s0, const int* __restrict__ d0,
                        const int* __restrict__ s1, const int* __restrict__ d1,
                        const int* __restrict__ s2, const int* __restrict__ d2,
                        const int* __restrict__ s3, const int* __restrict__ d3,
                        int E, int nDrug, int nGene) {
    int i = blockIdx.x * blockDim.x + threadIdx.x;
    const int *s, *d; int off, j;
    if (i < E)          { s = s0; d = d0; off = 0;                 j = i; }
    else if (i < 2 * E) { s = s1; d = d1; off = nDrug;             j = i - E; }
    else if (i < 3 * E) { s = s2; d = d2; off = 2 * nDrug;         j = i - 2 * E; }
    else if (i < 4 * E) { s = s3; d = d3; off = 2 * nDrug + nGene; j = i - 3 * E; }
    else return;
    int dd = __ldg(d + j);
    int pos = atomicAdd(&g_cursor[off + dd], 1);
    g_ebuf[pos] = __ldg(s + j);
}

// ---------------- projection GEMM (fp16 m16n16k16), A shared across both yh ----------------
#define HPAD 136
#define CPAD 136
#define GEMMH_SMEM (2 * 128 * HPAD * 2)     // 69632 B

__global__ void __launch_bounds__(512, 2)
gemm_all(const float* __restrict__ xD, const float* __restrict__ xG,
         const float* __restrict__ nsDD, const float* __restrict__ nsDG,
         const float* __restrict__ nsGD, const float* __restrict__ nsGG,
         const float* __restrict__ W_dd, const float* __restrict__ W_dg,
         const float* __restrict__ W_gd, const float* __restrict__ W_gg,
         __half* __restrict__ hD, __half* __restrict__ hG,
         int nDrug, int nGene, int nBlkD) {
    extern __shared__ char smraw[];
    __half* As = (__half*)smraw;                   // [128][HPAD] (lives across both yh)
    __half* Bs = (__half*)smraw + 128 * HPAD;      // [128][HPAD]
    float*  Cf = (float*)(smraw + 128 * HPAD * 2); // [64][CPAD] overlays Bs
    const int tid = threadIdx.x, wid = tid >> 5;

    const bool isD = blockIdx.x < nBlkD;
    const int bx = isD ? blockIdx.x : blockIdx.x - nBlkD;
    const float* x = isD ? xD : xG;
    const int    M = isD ? nDrug : nGene;
    __half*      h = isD ? hD : hG;
    const int rowBase = bx * 128;

    for (int i = tid; i < 4096; i += 512) {
        int m = i >> 5, kq = i & 31;
        int gr = rowBase + m;
        float4 v = make_float4(0.f, 0.f, 0.f, 0.f);
        if (gr < M) v = __ldg((const float4*)(x + (size_t)gr * DIM) + kq);
        __half2* p = (__half2*)&As[m * HPAD + kq * 4];
        p[0] = __floats2half2_rn(v.x, v.y);
        p[1] = __floats2half2_rn(v.z, v.w);
    }

    const int wrow = (wid >> 1) * 16;
    const int wcol = (wid & 1) * 64;

    #pragma unroll
    for (int yh = 0; yh < 2; yh++) {
        const float* W  = isD ? (yh ? W_dg : W_dd) : (yh ? W_gg : W_gd);
        const float* ns = isD ? (yh ? nsDG : nsDD) : (yh ? nsGG : nsGD);

        for (int i = tid; i < 128 * 32; i += 512) {
            int k = i >> 5, nq = i & 31;
            float4 v = __ldg((const float4*)(W + k * 128) + nq);
            __half2* p = (__half2*)&Bs[k * HPAD + nq * 4];
            p[0] = __floats2half2_rn(v.x, v.y);
            p[1] = __floats2half2_rn(v.z, v.w);
        }
        __syncthreads();

        wmma::fragment<wmma::accumulator, 16, 16, 16, float> c[4];
        #pragma unroll
        for (int t = 0; t < 4; t++) wmma::fill_fragment(c[t], 0.0f);
        #pragma unroll
        for (int ks = 0; ks < 8; ks++) {
            wmma::fragment<wmma::matrix_a, 16, 16, 16, __half, wmma::row_major> a;
            wmma::load_matrix_sync(a, &As[wrow * HPAD + ks * 16], HPAD);
            #pragma unroll
            for (int t = 0; t < 4; t++) {
                wmma::fragment<wmma::matrix_b, 16, 16, 16, __half, wmma::row_major> b;
                wmma::load_matrix_sync(b, &Bs[(ks * 16) * HPAD + wcol + t * 16], HPAD);
                wmma::mma_sync(c[t], a, b, c[t]);
            }
        }

        #pragma unroll
        for (int phase = 0; phase < 2; phase++) {
            __syncthreads();
            if ((wid >> 3) == phase) {
                float* Cw = Cf + (wrow & 63) * CPAD + wcol;
                #pragma unroll
                for (int t = 0; t < 4; t++)
                    wmma::store_matrix_sync(&Cw[t * 16], c[t], CPAD, wmma::mem_row_major);
            }
            __syncthreads();
            for (int i = tid; i < 64 * 64; i += 512) {
                int m = i >> 6, c2 = i & 63;
                int gr = rowBase + phase * 64 + m;
                if (gr < M) {
                    float s = __ldg(ns + gr);
                    const float* p = &Cf[m * CPAD + c2 * 2];
                    __half2* hp = (__half2*)(h + (size_t)gr * 256 + yh * 128);
                    hp[c2] = __floats2half2_rn(p[0] * s, p[1] * s);
                }
            }
        }
        __syncthreads();
    }
}

// ---------------- final gather: TWO warps per dst node; single predicated 8-batch loop ----------------
__global__ void __launch_bounds__(256)
gather_out(const float* __restrict__ bias, float* __restrict__ out,
           int nDrug, int nGene,
           int o_dd_d, int o_gd_d, int o_dg_d, int o_gg_d) {
    __shared__ float4 red[8][32];
    const int tid  = threadIdx.x;
    const int wid  = tid >> 5, lane = tid & 31;
    const int node = blockIdx.x * 4 + (wid >> 1);
    const int list = wid & 1;
    const int nNodes = nDrug + nGene;

    float4 acc = make_float4(0.f, 0.f, 0.f, 0.f);
    float nn = 0.f;

    if (node < nNodes) {
        const __half* h; int colOff, b, dg, odst;
        if (node < nDrug) {
            int r = node; colOff = 0;
            if (list == 0) { h = g_hD; b = __ldg(g_base + r);         odst = o_dd_d; }
            else           { h = g_hG; b = __ldg(g_base + nDrug + r); odst = o_gd_d; }
            dg = __ldg(g_deg + odst + r); nn = __ldg(g_norm + odst + r);
        } else {
            int r = node - nDrug; colOff = 128;
            if (list == 0) { h = g_hD; b = __ldg(g_base + 2 * nDrug + r);         odst = o_dg_d; }
            else           { h = g_hG; b = __ldg(g_base + 2 * nDrug + nGene + r); odst = o_gg_d; }
            dg = __ldg(g_deg + odst + r); nn = __ldg(g_norm + odst + r);
        }

        const uint2* hp = (const uint2*)(h + colOff);   // row s at hp + s*64 + lane
        const int e = b + dg;
        // Single predicated loop: OOR edge indices clamp to the last valid edge.
        // Duplicate row loads hit L1 (same line just fetched); contributions gated.
        for (int j = b; j < e; j += 8) {
            int s[8];
            #pragma unroll
            for (int q = 0; q < 8; q++) {
                int idx = j + q;
                s[q] = __ldg(g_ebuf + (idx < e ? idx : e - 1));
            }
            uint2 u[8];
            #pragma unroll
            for (int q = 0; q < 8; q++) u[q] = __ldg(hp + (size_t)s[q] * 64 + lane);
            #pragma unroll
            for (int q = 0; q < 8; q++) {
                if (j + q < e) {
                    float2 a = __half22float2(*(const __half2*)&u[q].x);
                    float2 c = __half22float2(*(const __half2*)&u[q].y);
                    acc.x += a.x; acc.y += a.y; acc.z += c.x; acc.w += c.y;
                }
            }
        }
    }
    acc.x *= nn; acc.y *= nn; acc.z *= nn; acc.w *= nn;
    red[wid][lane] = acc;
    __syncthreads();

    if (list == 0 && node < nNodes) {
        float4 o = red[wid + 1][lane];
        float4 bb = __ldg((const float4*)bias + lane);
        float4 v;
        v.x = fmaxf(acc.x + o.x + bb.x, 0.f);
        v.y = fmaxf(acc.y + o.y + bb.y, 0.f);
        v.z = fmaxf(acc.z + o.z + bb.z, 0.f);
        v.w = fmaxf(acc.w + o.w + bb.w, 0.f);

        float ss = v.x * v.x + v.y * v.y + v.z * v.z + v.w * v.w;
        #pragma unroll
        for (int off = 16; off > 0; off >>= 1)
            ss += __shfl_xor_sync(0xffffffffu, ss, off);
        float inv = 1.0f / fmaxf(sqrtf(ss), 1e-12f);
        v.x *= inv; v.y *= inv; v.z *= inv; v.w *= inv;

        *((float4*)(out + (size_t)node * DIM) + lane) = v;
    }
}

// ---------------- launch (fork/join overlap: {scan,bin} || {gemm}) ----------------
extern "C" void kernel_launch(void* const* d_in, const int* in_sizes, int n_in,
                              void* d_out, int out_size) {
    const float* x_drug = (const float*)d_in[0];
    const float* x_gene = (const float*)d_in[1];
    const float* W_dd   = (const float*)d_in[2];
    const float* W_dg   = (const float*)d_in[3];
    const float* W_gd   = (const float*)d_in[4];
    const float* W_gg   = (const float*)d_in[5];
    const float* h_bias = (const float*)d_in[6];
    const int* src_dd = (const int*)d_in[7];   const int* dst_dd = (const int*)d_in[8];
    const int* src_dg = (const int*)d_in[9];   const int* dst_dg = (const int*)d_in[10];
    const int* src_gd = (const int*)d_in[11];  const int* dst_gd = (const int*)d_in[12];
    const int* src_gg = (const int*)d_in[13];  const int* dst_gg = (const int*)d_in[14];
    float* out = (float*)d_out;

    const int E     = in_sizes[7];
    const int nDrug = in_sizes[0] / DIM;
    const int nGene = in_sizes[1] / DIM;

    const int o_dd_s = 0;
    const int o_dd_d = o_dd_s + nDrug;
    const int o_dg_s = o_dd_d + nDrug;
    const int o_dg_d = o_dg_s + nDrug;
    const int o_gd_s = o_dg_d + nGene;
    const int o_gd_d = o_gd_s + nGene;
    const int o_gg_s = o_gd_d + nDrug;
    const int o_gg_d = o_gg_s + nGene;
    const int nTot   = o_gg_d + nGene;          // 600000
    const int nScan  = 2 * nDrug + 2 * nGene;   // 300000

    float* normP;
    __half *hD, *hG;
    cudaGetSymbolAddress((void**)&normP, g_norm);
    cudaGetSymbolAddress((void**)&hD, g_hD);
    cudaGetSymbolAddress((void**)&hG, g_hG);

    static cudaStream_t sSide = nullptr;
    static cudaEvent_t evFork = nullptr, evJoin = nullptr;
    if (sSide == nullptr) {
        cudaStreamCreateWithFlags(&sSide, cudaStreamNonBlocking);
        cudaEventCreateWithFlags(&evFork, cudaEventDisableTiming);
        cudaEventCreateWithFlags(&evJoin, cudaEventDisableTiming);
    }

    zero_deg<<<(600000 / 4 + 255) / 256, 256>>>();

    const long long totDeg = 4LL * E;
    deg_all<<<(int)((totDeg + 255) / 256), 256>>>(
        src_dd, dst_dd, o_dd_s, o_dd_d,
        src_dg, dst_dg, o_dg_s, o_dg_d,
        src_gd, dst_gd, o_gd_s, o_gd_d,
        src_gg, dst_gg, o_gg_s, o_gg_d, E);

    norm_kernel<<<(nTot + 255) / 256, 256>>>(nTot);

    // fork: gemm on side stream (depends only on norms)
    cudaEventRecord(evFork, 0);
    cudaStreamWaitEvent(sSide, evFork, 0);

    cudaFuncSetAttribute(gemm_all, cudaFuncAttributeMaxDynamicSharedMemorySize, GEMMH_SMEM);
    const int nBlkD = (nDrug + 127) / 128;
    const int nBlkG = (nGene + 127) / 128;
    gemm_all<<<nBlkD + nBlkG, 512, GEMMH_SMEM, sSide>>>(
        x_drug, x_gene,
        normP + o_dd_s, normP + o_dg_s, normP + o_gd_s, normP + o_gg_s,
        W_dd, W_dg, W_gd, W_gg, hD, hG, nDrug, nGene, nBlkD);
    cudaEventRecord(evJoin, sSide);

    // main stream: scan + bin (independent of gemm)
    const int nScanBlk = (nScan + SCAN_BLK - 1) / SCAN_BLK;
    scan1<<<nScanBlk, 256>>>(nScan, nDrug, nGene, o_dd_d, o_gd_d, o_dg_d, o_gg_d);
    scan2<<<1, 512>>>(nScanBlk);
    scan3<<<(nScan + 255) / 256, 256>>>(nScan);

    bin_all<<<(int)((totDeg + 255) / 256), 256>>>(
        src_dd, dst_dd,
        src_gd, dst_gd,
        src_dg, dst_dg,
        src_gg, dst_gg, E, nDrug, nGene);

    // join: gather needs both bin (ebuf) and gemm (h)
    cudaStreamWaitEvent(0, evJoin, 0);
    gather_out<<<(nDrug + nGene + 3) / 4, 256>>>(
        h_bias, out, nDrug, nGene, o_dd_d, o_gd_d, o_dg_d, o_gg_d);
}

// round 16
// speedup vs baseline: 1.0318x; 1.0318x over previous
#include <cuda_runtime.h>
#include <cuda_fp16.h>
#include <cstdint>
#include <math.h>
#include <mma.h>

using namespace nvcuda;

#define DIM 128

// ---------------- scratch (device globals; no allocation allowed) ----------------
__device__ int    g_deg [600000];
__device__ float  g_norm[600000];
__device__ int    g_base  [300000];   // CSR row starts: [dd | gd | dg | gg] (by dst)
__device__ int    g_cursor[300000];
__device__ int    g_bsum  [512];
__device__ int    g_ebuf  [2400000];  // binned src indices
__device__ __half g_hD[100000ull * 256];  // drug proj: cols 0-127 = dd, 128-255 = dg
__device__ __half g_hG[ 50000ull * 256];  // gene proj: cols 0-127 = gd, 128-255 = gg

// ---------------- zero deg ----------------
__global__ void zero_deg() {
    int i = blockIdx.x * blockDim.x + threadIdx.x;
    if (i < 600000 / 4) ((int4*)g_deg)[i] = make_int4(0, 0, 0, 0);
}

// ---------------- degree counting, one side (4 etypes) ----------------
__global__ void deg_side(const int* __restrict__ a0, int o0,
                         const int* __restrict__ a1, int o1,
                         const int* __restrict__ a2, int o2,
                         const int* __restrict__ a3, int o3,
                         int E) {
    int i = blockIdx.x * blockDim.x + threadIdx.x;
    const int* a; int off, j;
    if (i < E)          { a = a0; off = o0; j = i; }
    else if (i < 2 * E) { a = a1; off = o1; j = i - E; }
    else if (i < 3 * E) { a = a2; off = o2; j = i - 2 * E; }
    else if (i < 4 * E) { a = a3; off = o3; j = i - 3 * E; }
    else return;
    atomicAdd(&g_deg[off + __ldg(a + j)], 1);
}

// ---------------- norm over 4 segments: first two of count nA, last two of count nB ----------------
__global__ void norm4(int oA0, int oA1, int oB0, int oB1, int nA, int nB) {
    int i = blockIdx.x * blockDim.x + threadIdx.x;
    int idx;
    if (i < nA)                 idx = oA0 + i;
    else if (i < 2 * nA)        idx = oA1 + i - nA;
    else if (i < 2 * nA + nB)   idx = oB0 + i - 2 * nA;
    else if (i < 2 * (nA + nB)) idx = oB1 + i - 2 * nA - nB;
    else return;
    g_norm[idx] = rsqrtf(fmaxf((float)g_deg[idx], 1.0f));
}

// ---------------- 3-phase exclusive scan over concatenated dst degrees ----------------
#define SCAN_BLK 1024
__global__ void scan1(int total, int nDrug, int nGene,
                      int o_dd_d, int o_gd_d, int o_dg_d, int o_gg_d) {
    __shared__ int sh[256];
    const int tid = threadIdx.x;
    const int base = blockIdx.x * SCAN_BLK + tid * 4;
    const int c1 = nDrug, c2 = 2 * nDrug, c3 = 2 * nDrug + nGene;
    int v[4], ssum = 0;
    #pragma unroll
    for (int q = 0; q < 4; q++) {
        int i = base + q, d = 0;
        if (i < total) {
            int idx;
            if (i < c1)      idx = o_dd_d + i;
            else if (i < c2) idx = o_gd_d + i - c1;
            else if (i < c3) idx = o_dg_d + i - c2;
            else             idx = o_gg_d + i - c3;
            d = g_deg[idx];
        }
        v[q] = d; ssum += d;
    }
    sh[tid] = ssum; __syncthreads();
    for (int off = 1; off < 256; off <<= 1) {
        int t = (tid >= off) ? sh[tid - off] : 0;
        __syncthreads();
        sh[tid] += t;
        __syncthreads();
    }
    int run = sh[tid] - ssum;
    if (tid == 255) g_bsum[blockIdx.x] = sh[255];
    #pragma unroll
    for (int q = 0; q < 4; q++) {
        int i = base + q;
        if (i < total) g_base[i] = run;
        run += v[q];
    }
}

__global__ void scan2(int n) {
    __shared__ int sh[512];
    int tid = threadIdx.x;
    int v = (tid < n) ? g_bsum[tid] : 0;
    sh[tid] = v; __syncthreads();
    for (int off = 1; off < 512; off <<= 1) {
        int t = (tid >= off) ? sh[tid - off] : 0;
        __syncthreads();
        sh[tid] += t;
        __syncthreads();
    }
    if (tid < n) g_bsum[tid] = sh[tid] - v;
}

__global__ void scan3(int total) {
    int i = blockIdx.x * blockDim.x + threadIdx.x;
    if (i < total) {
        int v = g_base[i] + g_bsum[i / SCAN_BLK];
        g_base[i] = v;
        g_cursor[i] = v;
    }
}

// ---------------- binning: ebuf[pos] = src (CSR by dst); segment order dd, gd, dg, gg ----------------
__global__ void bin_all(const int* __restrict__ s0, const int* __restrict__ d0,
                        const int* __restrict__ s1, const int* __restrict__ d1,
                        const int* __restrict__ s2, const int* __restrict__ d2,
                        const int* __restrict__ s3, const int* __restrict__ d3,
                        int E, int nDrug, int nGene) {
    int i = blockIdx.x * blockDim.x + threadIdx.x;
    const int *s, *d; int off, j;
    if (i < E)          { s = s0; d = d0; off = 0;                 j = i; }
    else if (i < 2 * E) { s = s1; d = d1; off = nDrug;             j = i - E; }
    else if (i < 3 * E) { s = s2; d = d2; off = 2 * nDrug;         j = i - 2 * E; }
    else if (i < 4 * E) { s = s3; d = d3; off = 2 * nDrug + nGene; j = i - 3 * E; }
    else return;
    int dd = __ldg(d + j);
    int pos = atomicAdd(&g_cursor[off + dd], 1);
    g_ebuf[pos] = __ldg(s + j);
}

// ---------------- projection GEMM (fp16 m16n16k16), A shared across both yh ----------------
#define HPAD 136
#define CPAD 136
#define GEMMH_SMEM (2 * 128 * HPAD * 2)     // 69632 B

__global__ void __launch_bounds__(512, 2)
gemm_all(const float* __restrict__ xD, const float* __restrict__ xG,
         const float* __restrict__ nsDD, const float* __restrict__ nsDG,
         const float* __restrict__ nsGD, const float* __restrict__ nsGG,
         const float* __restrict__ W_dd, const float* __restrict__ W_dg,
         const float* __restrict__ W_gd, const float* __restrict__ W_gg,
         __half* __restrict__ hD, __half* __restrict__ hG,
         int nDrug, int nGene, int nBlkD) {
    extern __shared__ char smraw[];
    __half* As = (__half*)smraw;                   // [128][HPAD] (lives across both yh)
    __half* Bs = (__half*)smraw + 128 * HPAD;      // [128][HPAD]
    float*  Cf = (float*)(smraw + 128 * HPAD * 2); // [64][CPAD] overlays Bs
    const int tid = threadIdx.x, wid = tid >> 5;

    const bool isD = blockIdx.x < nBlkD;
    const int bx = isD ? blockIdx.x : blockIdx.x - nBlkD;
    const float* x = isD ? xD : xG;
    const int    M = isD ? nDrug : nGene;
    __half*      h = isD ? hD : hG;
    const int rowBase = bx * 128;

    for (int i = tid; i < 4096; i += 512) {
        int m = i >> 5, kq = i & 31;
        int gr = rowBase + m;
        float4 v = make_float4(0.f, 0.f, 0.f, 0.f);
        if (gr < M) v = __ldg((const float4*)(x + (size_t)gr * DIM) + kq);
        __half2* p = (__half2*)&As[m * HPAD + kq * 4];
        p[0] = __floats2half2_rn(v.x, v.y);
        p[1] = __floats2half2_rn(v.z, v.w);
    }

    const int wrow = (wid >> 1) * 16;
    const int wcol = (wid & 1) * 64;

    #pragma unroll
    for (int yh = 0; yh < 2; yh++) {
        const float* W  = isD ? (yh ? W_dg : W_dd) : (yh ? W_gg : W_gd);
        const float* ns = isD ? (yh ? nsDG : nsDD) : (yh ? nsGG : nsGD);

        for (int i = tid; i < 128 * 32; i += 512) {
            int k = i >> 5, nq = i & 31;
            float4 v = __ldg((const float4*)(W + k * 128) + nq);
            __half2* p = (__half2*)&Bs[k * HPAD + nq * 4];
            p[0] = __floats2half2_rn(v.x, v.y);
            p[1] = __floats2half2_rn(v.z, v.w);
        }
        __syncthreads();

        wmma::fragment<wmma::accumulator, 16, 16, 16, float> c[4];
        #pragma unroll
        for (int t = 0; t < 4; t++) wmma::fill_fragment(c[t], 0.0f);
        #pragma unroll
        for (int ks = 0; ks < 8; ks++) {
            wmma::fragment<wmma::matrix_a, 16, 16, 16, __half, wmma::row_major> a;
            wmma::load_matrix_sync(a, &As[wrow * HPAD + ks * 16], HPAD);
            #pragma unroll
            for (int t = 0; t < 4; t++) {
                wmma::fragment<wmma::matrix_b, 16, 16, 16, __half, wmma::row_major> b;
                wmma::load_matrix_sync(b, &Bs[(ks * 16) * HPAD + wcol + t * 16], HPAD);
                wmma::mma_sync(c[t], a, b, c[t]);
            }
        }

        #pragma unroll
        for (int phase = 0; phase < 2; phase++) {
            __syncthreads();
            if ((wid >> 3) == phase) {
                float* Cw = Cf + (wrow & 63) * CPAD + wcol;
                #pragma unroll
                for (int t = 0; t < 4; t++)
                    wmma::store_matrix_sync(&Cw[t * 16], c[t], CPAD, wmma::mem_row_major);
            }
            __syncthreads();
            for (int i = tid; i < 64 * 64; i += 512) {
                int m = i >> 6, c2 = i & 63;
                int gr = rowBase + phase * 64 + m;
                if (gr < M) {
                    float s = __ldg(ns + gr);
                    const float* p = &Cf[m * CPAD + c2 * 2];
                    __half2* hp = (__half2*)(h + (size_t)gr * 256 + yh * 128);
                    hp[c2] = __floats2half2_rn(p[0] * s, p[1] * s);
                }
            }
        }
        __syncthreads();
    }
}

// ---------------- final gather: TWO warps per dst node (R13 version) ----------------
__global__ void __launch_bounds__(256)
gather_out(const float* __restrict__ bias, float* __restrict__ out,
           int nDrug, int nGene,
           int o_dd_d, int o_gd_d, int o_dg_d, int o_gg_d) {
    __shared__ float4 red[8][32];
    const int tid  = threadIdx.x;
    const int wid  = tid >> 5, lane = tid & 31;
    const int node = blockIdx.x * 4 + (wid >> 1);
    const int list = wid & 1;
    const int nNodes = nDrug + nGene;

    float4 acc = make_float4(0.f, 0.f, 0.f, 0.f);
    float nn = 0.f;

    if (node < nNodes) {
        const __half* h; int colOff, b, dg, odst;
        if (node < nDrug) {
            int r = node; colOff = 0;
            if (list == 0) { h = g_hD; b = __ldg(g_base + r);         odst = o_dd_d; }
            else           { h = g_hG; b = __ldg(g_base + nDrug + r); odst = o_gd_d; }
            dg = __ldg(g_deg + odst + r); nn = __ldg(g_norm + odst + r);
        } else {
            int r = node - nDrug; colOff = 128;
            if (list == 0) { h = g_hD; b = __ldg(g_base + 2 * nDrug + r);         odst = o_dg_d; }
            else           { h = g_hG; b = __ldg(g_base + 2 * nDrug + nGene + r); odst = o_gg_d; }
            dg = __ldg(g_deg + odst + r); nn = __ldg(g_norm + odst + r);
        }

        const uint2* hp = (const uint2*)(h + colOff);
        int j = b; const int e = b + dg;
        for (; j + 8 <= e; j += 8) {
            int s[8];
            #pragma unroll
            for (int q = 0; q < 8; q++) s[q] = __ldg(g_ebuf + j + q);
            uint2 u[8];
            #pragma unroll
            for (int q = 0; q < 8; q++) u[q] = __ldg(hp + (size_t)s[q] * 64 + lane);
            #pragma unroll
            for (int q = 0; q < 8; q++) {
                float2 a = __half22float2(*(const __half2*)&u[q].x);
                float2 c = __half22float2(*(const __half2*)&u[q].y);
                acc.x += a.x; acc.y += a.y; acc.z += c.x; acc.w += c.y;
            }
        }
        for (; j + 2 <= e; j += 2) {
            int s0 = __ldg(g_ebuf + j), s1 = __ldg(g_ebuf + j + 1);
            uint2 u0 = __ldg(hp + (size_t)s0 * 64 + lane);
            uint2 u1 = __ldg(hp + (size_t)s1 * 64 + lane);
            float2 a0 = __half22float2(*(const __half2*)&u0.x);
            float2 c0 = __half22float2(*(const __half2*)&u0.y);
            float2 a1 = __half22float2(*(const __half2*)&u1.x);
            float2 c1 = __half22float2(*(const __half2*)&u1.y);
            acc.x += a0.x + a1.x; acc.y += a0.y + a1.y;
            acc.z += c0.x + c1.x; acc.w += c0.y + c1.y;
        }
        if (j < e) {
            int s = __ldg(g_ebuf + j);
            uint2 u = __ldg(hp + (size_t)s * 64 + lane);
            float2 a = __half22float2(*(const __half2*)&u.x);
            float2 c = __half22float2(*(const __half2*)&u.y);
            acc.x += a.x; acc.y += a.y; acc.z += c.x; acc.w += c.y;
        }
    }
    acc.x *= nn; acc.y *= nn; acc.z *= nn; acc.w *= nn;
    red[wid][lane] = acc;
    __syncthreads();

    if (list == 0 && node < nNodes) {
        float4 o = red[wid + 1][lane];
        float4 bb = __ldg((const float4*)bias + lane);
        float4 v;
        v.x = fmaxf(acc.x + o.x + bb.x, 0.f);
        v.y = fmaxf(acc.y + o.y + bb.y, 0.f);
        v.z = fmaxf(acc.z + o.z + bb.z, 0.f);
        v.w = fmaxf(acc.w + o.w + bb.w, 0.f);

        float ss = v.x * v.x + v.y * v.y + v.z * v.z + v.w * v.w;
        #pragma unroll
        for (int off = 16; off > 0; off >>= 1)
            ss += __shfl_xor_sync(0xffffffffu, ss, off);
        float inv = 1.0f / fmaxf(sqrtf(ss), 1e-12f);
        v.x *= inv; v.y *= inv; v.z *= inv; v.w *= inv;

        *((float4*)(out + (size_t)node * DIM) + lane) = v;
    }
}

// ---------------- launch: early fork — {src-deg,norm,gemm} || {dst-deg,norm,scan,bin} ----------------
extern "C" void kernel_launch(void* const* d_in, const int* in_sizes, int n_in,
                              void* d_out, int out_size) {
    const float* x_drug = (const float*)d_in[0];
    const float* x_gene = (const float*)d_in[1];
    const float* W_dd   = (const float*)d_in[2];
    const float* W_dg   = (const float*)d_in[3];
    const float* W_gd   = (const float*)d_in[4];
    const float* W_gg   = (const float*)d_in[5];
    const float* h_bias = (const float*)d_in[6];
    const int* src_dd = (const int*)d_in[7];   const int* dst_dd = (const int*)d_in[8];
    const int* src_dg = (const int*)d_in[9];   const int* dst_dg = (const int*)d_in[10];
    const int* src_gd = (const int*)d_in[11];  const int* dst_gd = (const int*)d_in[12];
    const int* src_gg = (const int*)d_in[13];  const int* dst_gg = (const int*)d_in[14];
    float* out = (float*)d_out;

    const int E     = in_sizes[7];
    const int nDrug = in_sizes[0] / DIM;
    const int nGene = in_sizes[1] / DIM;

    const int o_dd_s = 0;
    const int o_dd_d = o_dd_s + nDrug;
    const int o_dg_s = o_dd_d + nDrug;
    const int o_dg_d = o_dg_s + nDrug;
    const int o_gd_s = o_dg_d + nGene;
    const int o_gd_d = o_gd_s + nGene;
    const int o_gg_s = o_gd_d + nDrug;
    const int o_gg_d = o_gg_s + nGene;
    const int nScan  = 2 * nDrug + 2 * nGene;   // 300000

    float* normP;
    __half *hD, *hG;
    cudaGetSymbolAddress((void**)&normP, g_norm);
    cudaGetSymbolAddress((void**)&hD, g_hD);
    cudaGetSymbolAddress((void**)&hG, g_hG);

    static cudaStream_t sSide = nullptr;
    static cudaEvent_t evFork = nullptr, evJoin = nullptr;
    if (sSide == nullptr) {
        cudaStreamCreateWithFlags(&sSide, cudaStreamNonBlocking);
        cudaEventCreateWithFlags(&evFork, cudaEventDisableTiming);
        cudaEventCreateWithFlags(&evJoin, cudaEventDisableTiming);
    }

    zero_deg<<<(600000 / 4 + 255) / 256, 256>>>();

    // fork right after zero
    cudaEventRecord(evFork, 0);
    cudaStreamWaitEvent(sSide, evFork, 0);

    const long long totE = 4LL * E;
    const int degBlocks = (int)((totE + 255) / 256);

    // ---- side stream: src degrees -> src norms -> gemm ----
    deg_side<<<degBlocks, 256, 0, sSide>>>(
        src_dd, o_dd_s, src_dg, o_dg_s, src_gd, o_gd_s, src_gg, o_gg_s, E);
    // src segment sizes: dd_s=nDrug, dg_s=nDrug, gd_s=nGene, gg_s=nGene
    norm4<<<(nScan + 255) / 256, 256, 0, sSide>>>(
        o_dd_s, o_dg_s, o_gd_s, o_gg_s, nDrug, nGene);

    cudaFuncSetAttribute(gemm_all, cudaFuncAttributeMaxDynamicSharedMemorySize, GEMMH_SMEM);
    const int nBlkD = (nDrug + 127) / 128;
    const int nBlkG = (nGene + 127) / 128;
    gemm_all<<<nBlkD + nBlkG, 512, GEMMH_SMEM, sSide>>>(
        x_drug, x_gene,
        normP + o_dd_s, normP + o_dg_s, normP + o_gd_s, normP + o_gg_s,
        W_dd, W_dg, W_gd, W_gg, hD, hG, nDrug, nGene, nBlkD);
    cudaEventRecord(evJoin, sSide);

    // ---- main stream: dst degrees -> dst norms -> scan -> bin ----
    deg_side<<<degBlocks, 256>>>(
        dst_dd, o_dd_d, dst_dg, o_dg_d, dst_gd, o_gd_d, dst_gg, o_gg_d, E);
    // dst segment sizes: dd_d=nDrug, gd_d=nDrug, dg_d=nGene, gg_d=nGene
    // (FIX vs R15: order by size — drug-sized first, gene-sized second)
    norm4<<<(nScan + 255) / 256, 256>>>(
        o_dd_d, o_gd_d, o_dg_d, o_gg_d, nDrug, nGene);

    const int nScanBlk = (nScan + SCAN_BLK - 1) / SCAN_BLK;
    scan1<<<nScanBlk, 256>>>(nScan, nDrug, nGene, o_dd_d, o_gd_d, o_dg_d, o_gg_d);
    scan2<<<1, 512>>>(nScanBlk);
    scan3<<<(nScan + 255) / 256, 256>>>(nScan);

    bin_all<<<degBlocks, 256>>>(
        src_dd, dst_dd,
        src_gd, dst_gd,
        src_dg, dst_dg,
        src_gg, dst_gg, E, nDrug, nGene);

    // join: gather needs both bin (ebuf, main) and gemm (h, side)
    cudaStreamWaitEvent(0, evJoin, 0);
    gather_out<<<(nDrug + nGene + 3) / 4, 256>>>(
        h_bias, out, nDrug, nGene, o_dd_d, o_gd_d, o_dg_d, o_gg_d);
}

// round 17
// speedup vs baseline: 1.0716x; 1.0385x over previous
#include <cuda_runtime.h>
#include <cuda_fp16.h>
#include <cstdint>
#include <math.h>
#include <mma.h>

using namespace nvcuda;

#define DIM 128

// ---------------- scratch (device globals; no allocation allowed) ----------------
__device__ int    g_deg [600000];
__device__ float  g_norm[600000];
__device__ int    g_base  [300000];   // CSR row starts: [dd | gd | dg | gg] (by dst)
__device__ int    g_cursor[300000];
__device__ int    g_bsum  [512];
__device__ int    g_ebuf  [2400000];  // binned src indices
__device__ __half g_hD[100000ull * 256];  // drug proj: cols 0-127 = dd, 128-255 = dg
__device__ __half g_hG[ 50000ull * 256];  // gene proj: cols 0-127 = gd, 128-255 = gg
__device__ __half g_x16[150000ull * 128]; // fp16 image of [x_drug ; x_gene]
__device__ __half g_W16[4 * 128 * 128];   // fp16 images: [W_dd | W_dg | W_gd | W_gg]

// ---------------- cp.async helper ----------------
__device__ __forceinline__ void cp16(void* dst_smem, const void* src_gmem, int src_sz) {
    uint32_t d = (uint32_t)__cvta_generic_to_shared(dst_smem);
    asm volatile("cp.async.cg.shared.global [%0], [%1], 16, %2;"
                 :: "r"(d), "l"(src_gmem), "r"(src_sz));
}

// ---------------- fp16 image builders (no deps; run at t=0 on side stream) ----------------
__global__ void cvt_x16(const float* __restrict__ xD, const float* __restrict__ xG,
                        int nD, int nG) {
    int t = blockIdx.x * blockDim.x + threadIdx.x;       // one float4 each
    int qD = nD * 32, qTot = (nD + nG) * 32;
    if (t >= qTot) return;
    float4 v = (t < qD) ? __ldg((const float4*)xD + t)
                        : __ldg((const float4*)xG + (t - qD));
    __half2* o = (__half2*)g_x16 + (size_t)t * 2;
    o[0] = __floats2half2_rn(v.x, v.y);
    o[1] = __floats2half2_rn(v.z, v.w);
}

__global__ void cvt_w16(const float* __restrict__ W0, const float* __restrict__ W1,
                        const float* __restrict__ W2, const float* __restrict__ W3) {
    int t = blockIdx.x * blockDim.x + threadIdx.x;       // one float4 each; 16384 total
    if (t >= 4 * 4096) return;
    int wsel = t >> 12, q = t & 4095;
    const float* W = (wsel == 0) ? W0 : (wsel == 1) ? W1 : (wsel == 2) ? W2 : W3;
    float4 v = __ldg((const float4*)W + q);
    __half2* o = (__half2*)g_W16 + (size_t)t * 2;
    o[0] = __floats2half2_rn(v.x, v.y);
    o[1] = __floats2half2_rn(v.z, v.w);
}

// ---------------- zero deg ----------------
__global__ void zero_deg() {
    int i = blockIdx.x * blockDim.x + threadIdx.x;
    if (i < 600000 / 4) ((int4*)g_deg)[i] = make_int4(0, 0, 0, 0);
}

// ---------------- degree counting, one side (4 etypes) ----------------
__global__ void deg_side(const int* __restrict__ a0, int o0,
                         const int* __restrict__ a1, int o1,
                         const int* __restrict__ a2, int o2,
                         const int* __restrict__ a3, int o3,
                         int E) {
    int i = blockIdx.x * blockDim.x + threadIdx.x;
    const int* a; int off, j;
    if (i < E)          { a = a0; off = o0; j = i; }
    else if (i < 2 * E) { a = a1; off = o1; j = i - E; }
    else if (i < 3 * E) { a = a2; off = o2; j = i - 2 * E; }
    else if (i < 4 * E) { a = a3; off = o3; j = i - 3 * E; }
    else return;
    atomicAdd(&g_deg[off + __ldg(a + j)], 1);
}

// ---------------- norm over 4 segments: first two of count nA, last two of count nB ----------------
__global__ void norm4(int oA0, int oA1, int oB0, int oB1, int nA, int nB) {
    int i = blockIdx.x * blockDim.x + threadIdx.x;
    int idx;
    if (i < nA)                 idx = oA0 + i;
    else if (i < 2 * nA)        idx = oA1 + i - nA;
    else if (i < 2 * nA + nB)   idx = oB0 + i - 2 * nA;
    else if (i < 2 * (nA + nB)) idx = oB1 + i - 2 * nA - nB;
    else return;
    g_norm[idx] = rsqrtf(fmaxf((float)g_deg[idx], 1.0f));
}

// ---------------- 3-phase exclusive scan over concatenated dst degrees ----------------
#define SCAN_BLK 1024
__global__ void scan1(int total, int nDrug, int nGene,
                      int o_dd_d, int o_gd_d, int o_dg_d, int o_gg_d) {
    __shared__ int sh[256];
    const int tid = threadIdx.x;
    const int base = blockIdx.x * SCAN_BLK + tid * 4;
    const int c1 = nDrug, c2 = 2 * nDrug, c3 = 2 * nDrug + nGene;
    int v[4], ssum = 0;
    #pragma unroll
    for (int q = 0; q < 4; q++) {
        int i = base + q, d = 0;
        if (i < total) {
            int idx;
            if (i < c1)      idx = o_dd_d + i;
            else if (i < c2) idx = o_gd_d + i - c1;
            else if (i < c3) idx = o_dg_d + i - c2;
            else             idx = o_gg_d + i - c3;
            d = g_deg[idx];
        }
        v[q] = d; ssum += d;
    }
    sh[tid] = ssum; __syncthreads();
    for (int off = 1; off < 256; off <<= 1) {
        int t = (tid >= off) ? sh[tid - off] : 0;
        __syncthreads();
        sh[tid] += t;
        __syncthreads();
    }
    int run = sh[tid] - ssum;
    if (tid == 255) g_bsum[blockIdx.x] = sh[255];
    #pragma unroll
    for (int q = 0; q < 4; q++) {
        int i = base + q;
        if (i < total) g_base[i] = run;
        run += v[q];
    }
}

__global__ void scan2(int n) {
    __shared__ int sh[512];
    int tid = threadIdx.x;
    int v = (tid < n) ? g_bsum[tid] : 0;
    sh[tid] = v; __syncthreads();
    for (int off = 1; off < 512; off <<= 1) {
        int t = (tid >= off) ? sh[tid - off] : 0;
        __syncthreads();
        sh[tid] += t;
        __syncthreads();
    }
    if (tid < n) g_bsum[tid] = sh[tid] - v;
}

__global__ void scan3(int total) {
    int i = blockIdx.x * blockDim.x + threadIdx.x;
    if (i < total) {
        int v = g_base[i] + g_bsum[i / SCAN_BLK];
        g_base[i] = v;
        g_cursor[i] = v;
    }
}

// ---------------- binning: ebuf[pos] = src (CSR by dst); segment order dd, gd, dg, gg ----------------
__global__ void bin_all(const int* __restrict__ s0, const int* __restrict__ d0,
                        const int* __restrict__ s1, const int* __restrict__ d1,
                        const int* __restrict__ s2, const int* __restrict__ d2,
                        const int* __restrict__ s3, const int* __restrict__ d3,
                        int E, int nDrug, int nGene) {
    int i = blockIdx.x * blockDim.x + threadIdx.x;
    const int *s, *d; int off, j;
    if (i < E)          { s = s0; d = d0; off = 0;                 j = i; }
    else if (i < 2 * E) { s = s1; d = d1; off = nDrug;             j = i - E; }
    else if (i < 3 * E) { s = s2; d = d2; off = 2 * nDrug;         j = i - 2 * E; }
    else if (i < 4 * E) { s = s3; d = d3; off = 2 * nDrug + nGene; j = i - 3 * E; }
    else return;
    int dd = __ldg(d + j);
    int pos = atomicAdd(&g_cursor[off + dd], 1);
    g_ebuf[pos] = __ldg(s + j);
}

// ---------------- projection GEMM (fp16 m16n16k16), cp.async staging, A shared across yh ----------------
#define HPAD 136
#define CPAD 136
#define GEMMH_SMEM (2 * 128 * HPAD * 2)     // 69632 B

__global__ void __launch_bounds__(512, 2)
gemm_all(const float* __restrict__ nsDD, const float* __restrict__ nsDG,
         const float* __restrict__ nsGD, const float* __restrict__ nsGG,
         __half* __restrict__ hD, __half* __restrict__ hG,
         int nDrug, int nGene, int nBlkD) {
    extern __shared__ char smraw[];
    __half* As = (__half*)smraw;                   // [128][HPAD] (lives across both yh)
    __half* Bs = (__half*)smraw + 128 * HPAD;      // [128][HPAD]
    float*  Cf = (float*)(smraw + 128 * HPAD * 2); // [64][CPAD] overlays Bs
    const int tid = threadIdx.x, wid = tid >> 5;

    const bool isD = blockIdx.x < nBlkD;
    const int bx = isD ? blockIdx.x : blockIdx.x - nBlkD;
    const int    M = isD ? nDrug : nGene;
    __half*      h = isD ? hD : hG;
    const int rowBase = bx * 128;
    const int xoff = isD ? 0 : nDrug;

    // Stage A via cp.async from fp16 x image (OOB rows zero-filled via src-size=0)
    for (int i = tid; i < 2048; i += 512) {
        int m = i >> 4, cq = i & 15;
        int gr = rowBase + m;
        int grc = (gr < M) ? gr : (M - 1);
        cp16(As + m * HPAD + cq * 8,
             g_x16 + ((size_t)(xoff + grc) * 128 + cq * 8),
             (gr < M) ? 16 : 0);
    }

    const int wrow = (wid >> 1) * 16;
    const int wcol = (wid & 1) * 64;

    #pragma unroll
    for (int yh = 0; yh < 2; yh++) {
        const int widx = isD ? yh : (2 + yh);   // g_W16 order: dd, dg, gd, gg
        const float* ns = isD ? (yh ? nsDG : nsDD) : (yh ? nsGG : nsGD);
        const __half* w16 = g_W16 + (size_t)widx * 16384;

        // Stage B via cp.async
        for (int i = tid; i < 2048; i += 512) {
            int m = i >> 4, cq = i & 15;
            cp16(Bs + m * HPAD + cq * 8, w16 + m * 128 + cq * 8, 16);
        }
        asm volatile("cp.async.commit_group;" ::: "memory");
        asm volatile("cp.async.wait_group 0;" ::: "memory");
        __syncthreads();

        wmma::fragment<wmma::accumulator, 16, 16, 16, float> c[4];
        #pragma unroll
        for (int t = 0; t < 4; t++) wmma::fill_fragment(c[t], 0.0f);
        #pragma unroll
        for (int ks = 0; ks < 8; ks++) {
            wmma::fragment<wmma::matrix_a, 16, 16, 16, __half, wmma::row_major> a;
            wmma::load_matrix_sync(a, &As[wrow * HPAD + ks * 16], HPAD);
            #pragma unroll
            for (int t = 0; t < 4; t++) {
                wmma::fragment<wmma::matrix_b, 16, 16, 16, __half, wmma::row_major> b;
                wmma::load_matrix_sync(b, &Bs[(ks * 16) * HPAD + wcol + t * 16], HPAD);
                wmma::mma_sync(c[t], a, b, c[t]);
            }
        }

        #pragma unroll
        for (int phase = 0; phase < 2; phase++) {
            __syncthreads();
            if ((wid >> 3) == phase) {
                float* Cw = Cf + (wrow & 63) * CPAD + wcol;
                #pragma unroll
                for (int t = 0; t < 4; t++)
                    wmma::store_matrix_sync(&Cw[t * 16], c[t], CPAD, wmma::mem_row_major);
            }
            __syncthreads();
            for (int i = tid; i < 64 * 64; i += 512) {
                int m = i >> 6, c2 = i & 63;
                int gr = rowBase + phase * 64 + m;
                if (gr < M) {
                    float s = __ldg(ns + gr);
                    const float* p = &Cf[m * CPAD + c2 * 2];
                    __half2* hp = (__half2*)(h + (size_t)gr * 256 + yh * 128);
                    hp[c2] = __floats2half2_rn(p[0] * s, p[1] * s);
                }
            }
        }
        __syncthreads();
    }
}

// ---------------- final gather: TWO warps per dst node (R13 version) ----------------
__global__ void __launch_bounds__(256)
gather_out(const float* __restrict__ bias, float* __restrict__ out,
           int nDrug, int nGene,
           int o_dd_d, int o_gd_d, int o_dg_d, int o_gg_d) {
    __shared__ float4 red[8][32];
    const int tid  = threadIdx.x;
    const int wid  = tid >> 5, lane = tid & 31;
    const int node = blockIdx.x * 4 + (wid >> 1);
    const int list = wid & 1;
    const int nNodes = nDrug + nGene;

    float4 acc = make_float4(0.f, 0.f, 0.f, 0.f);
    float nn = 0.f;

    if (node < nNodes) {
        const __half* h; int colOff, b, dg, odst;
        if (node < nDrug) {
            int r = node; colOff = 0;
            if (list == 0) { h = g_hD; b = __ldg(g_base + r);         odst = o_dd_d; }
            else           { h = g_hG; b = __ldg(g_base + nDrug + r); odst = o_gd_d; }
            dg = __ldg(g_deg + odst + r); nn = __ldg(g_norm + odst + r);
        } else {
            int r = node - nDrug; colOff = 128;
            if (list == 0) { h = g_hD; b = __ldg(g_base + 2 * nDrug + r);         odst = o_dg_d; }
            else           { h = g_hG; b = __ldg(g_base + 2 * nDrug + nGene + r); odst = o_gg_d; }
            dg = __ldg(g_deg + odst + r); nn = __ldg(g_norm + odst + r);
        }

        const uint2* hp = (const uint2*)(h + colOff);
        int j = b; const int e = b + dg;
        for (; j + 8 <= e; j += 8) {
            int s[8];
            #pragma unroll
            for (int q = 0; q < 8; q++) s[q] = __ldg(g_ebuf + j + q);
            uint2 u[8];
            #pragma unroll
            for (int q = 0; q < 8; q++) u[q] = __ldg(hp + (size_t)s[q] * 64 + lane);
            #pragma unroll
            for (int q = 0; q < 8; q++) {
                float2 a = __half22float2(*(const __half2*)&u[q].x);
                float2 c = __half22float2(*(const __half2*)&u[q].y);
                acc.x += a.x; acc.y += a.y; acc.z += c.x; acc.w += c.y;
            }
        }
        for (; j + 2 <= e; j += 2) {
            int s0 = __ldg(g_ebuf + j), s1 = __ldg(g_ebuf + j + 1);
            uint2 u0 = __ldg(hp + (size_t)s0 * 64 + lane);
            uint2 u1 = __ldg(hp + (size_t)s1 * 64 + lane);
            float2 a0 = __half22float2(*(const __half2*)&u0.x);
            float2 c0 = __half22float2(*(const __half2*)&u0.y);
            float2 a1 = __half22float2(*(const __half2*)&u1.x);
            float2 c1 = __half22float2(*(const __half2*)&u1.y);
            acc.x += a0.x + a1.x; acc.y += a0.y + a1.y;
            acc.z += c0.x + c1.x; acc.w += c0.y + c1.y;
        }
        if (j < e) {
            int s = __ldg(g_ebuf + j);
            uint2 u = __ldg(hp + (size_t)s * 64 + lane);
            float2 a = __half22float2(*(const __half2*)&u.x);
            float2 c = __half22float2(*(const __half2*)&u.y);
            acc.x += a.x; acc.y += a.y; acc.z += c.x; acc.w += c.y;
        }
    }
    acc.x *= nn; acc.y *= nn; acc.z *= nn; acc.w *= nn;
    red[wid][lane] = acc;
    __syncthreads();

    if (list == 0 && node < nNodes) {
        float4 o = red[wid + 1][lane];
        float4 bb = __ldg((const float4*)bias + lane);
        float4 v;
        v.x = fmaxf(acc.x + o.x + bb.x, 0.f);
        v.y = fmaxf(acc.y + o.y + bb.y, 0.f);
        v.z = fmaxf(acc.z + o.z + bb.z, 0.f);
        v.w = fmaxf(acc.w + o.w + bb.w, 0.f);

        float ss = v.x * v.x + v.y * v.y + v.z * v.z + v.w * v.w;
        #pragma unroll
        for (int off = 16; off > 0; off >>= 1)
            ss += __shfl_xor_sync(0xffffffffu, ss, off);
        float inv = 1.0f / fmaxf(sqrtf(ss), 1e-12f);
        v.x *= inv; v.y *= inv; v.z *= inv; v.w *= inv;

        *((float4*)(out + (size_t)node * DIM) + lane) = v;
    }
}

// ---------------- launch: side={cvt, gemm}; main={zero, src-deg, norm, dst-deg, scan, bin, gather} ----------------
extern "C" void kernel_launch(void* const* d_in, const int* in_sizes, int n_in,
                              void* d_out, int out_size) {
    const float* x_drug = (const float*)d_in[0];
    const float* x_gene = (const float*)d_in[1];
    const float* W_dd   = (const float*)d_in[2];
    const float* W_dg   = (const float*)d_in[3];
    const float* W_gd   = (const float*)d_in[4];
    const float* W_gg   = (const float*)d_in[5];
    const float* h_bias = (const float*)d_in[6];
    const int* src_dd = (const int*)d_in[7];   const int* dst_dd = (const int*)d_in[8];
    const int* src_dg = (const int*)d_in[9];   const int* dst_dg = (const int*)d_in[10];
    const int* src_gd = (const int*)d_in[11];  const int* dst_gd = (const int*)d_in[12];
    const int* src_gg = (const int*)d_in[13];  const int* dst_gg = (const int*)d_in[14];
    float* out = (float*)d_out;

    const int E     = in_sizes[7];
    const int nDrug = in_sizes[0] / DIM;
    const int nGene = in_sizes[1] / DIM;

    const int o_dd_s = 0;
    const int o_dd_d = o_dd_s + nDrug;
    const int o_dg_s = o_dd_d + nDrug;
    const int o_dg_d = o_dg_s + nDrug;
    const int o_gd_s = o_dg_d + nGene;
    const int o_gd_d = o_gd_s + nGene;
    const int o_gg_s = o_gd_d + nDrug;
    const int o_gg_d = o_gg_s + nGene;
    const int nScan  = 2 * nDrug + 2 * nGene;   // 300000

    float* normP;
    __half *hD, *hG;
    cudaGetSymbolAddress((void**)&normP, g_norm);
    cudaGetSymbolAddress((void**)&hD, g_hD);
    cudaGetSymbolAddress((void**)&hG, g_hG);

    static cudaStream_t sSide = nullptr;
    static cudaEvent_t evSrc = nullptr, evJoin = nullptr;
    if (sSide == nullptr) {
        cudaStreamCreateWithFlags(&sSide, cudaStreamNonBlocking);
        cudaEventCreateWithFlags(&evSrc, cudaEventDisableTiming);
        cudaEventCreateWithFlags(&evJoin, cudaEventDisableTiming);
    }

    const long long totE = 4LL * E;
    const int degBlocks = (int)((totE + 255) / 256);

    // ---- side stream: fp16 image builders (no deps) ----
    const int qTot = (nDrug + nGene) * 32;
    cvt_x16<<<(qTot + 255) / 256, 256, 0, sSide>>>(x_drug, x_gene, nDrug, nGene);
    cvt_w16<<<(4 * 4096 + 255) / 256, 256, 0, sSide>>>(W_dd, W_dg, W_gd, W_gg);

    // ---- main: zero -> src degrees -> src norms ----
    zero_deg<<<(600000 / 4 + 255) / 256, 256>>>();
    deg_side<<<degBlocks, 256>>>(
        src_dd, o_dd_s, src_dg, o_dg_s, src_gd, o_gd_s, src_gg, o_gg_s, E);
    norm4<<<(nScan + 255) / 256, 256>>>(
        o_dd_s, o_dg_s, o_gd_s, o_gg_s, nDrug, nGene);
    cudaEventRecord(evSrc, 0);

    // ---- side: gemm (needs fp16 images + src norms) ----
    cudaStreamWaitEvent(sSide, evSrc, 0);
    cudaFuncSetAttribute(gemm_all, cudaFuncAttributeMaxDynamicSharedMemorySize, GEMMH_SMEM);
    const int nBlkD = (nDrug + 127) / 128;
    const int nBlkG = (nGene + 127) / 128;
    gemm_all<<<nBlkD + nBlkG, 512, GEMMH_SMEM, sSide>>>(
        normP + o_dd_s, normP + o_dg_s, normP + o_gd_s, normP + o_gg_s,
        hD, hG, nDrug, nGene, nBlkD);
    cudaEventRecord(evJoin, sSide);

    // ---- main: dst degrees -> dst norms -> scan -> bin ----
    deg_side<<<degBlocks, 256>>>(
        dst_dd, o_dd_d, dst_dg, o_dg_d, dst_gd, o_gd_d, dst_gg, o_gg_d, E);
    norm4<<<(nScan + 255) / 256, 256>>>(
        o_dd_d, o_gd_d, o_dg_d, o_gg_d, nDrug, nGene);   // drug-sized segs first

    const int nScanBlk = (nScan + SCAN_BLK - 1) / SCAN_BLK;
    scan1<<<nScanBlk, 256>>>(nScan, nDrug, nGene, o_dd_d, o_gd_d, o_dg_d, o_gg_d);
    scan2<<<1, 512>>>(nScanBlk);
    scan3<<<(nScan + 255) / 256, 256>>>(nScan);

    bin_all<<<degBlocks, 256>>>(
        src_dd, dst_dd,
        src_gd, dst_gd,
        src_dg, dst_dg,
        src_gg, dst_gg, E, nDrug, nGene);

    // join: gather needs both bin (ebuf, main) and gemm (h, side)
    cudaStreamWaitEvent(0, evJoin, 0);
    gather_out<<<(nDrug + nGene + 3) / 4, 256>>>(
        h_bias, out, nDrug, nGene, o_dd_d, o_gd_d, o_dg_d, o_gg_d);
}